// round 15
// baseline (speedup 1.0000x reference)
#include <cuda_runtime.h>

#define HH 128
#define WW 128
#define NPIX (HH*WW)
#define NWORDS (NPIX/32)   // 512
#define NB 16
#define NTHREADS 1024
#define PITCH 129

__device__ float g_geomloss[NB];
__device__ float g_comploss[NB];
__device__ int   g_done = 0;   // self-resetting ticket (counts to 32)

// ---- lock-free union-find with atomicMin path-halving (monotone => race-safe) ----
__device__ __forceinline__ int find_root(int* lab, int a) {
    for (;;) {
        int p = lab[a];
        if (p == a) return a;
        int gp = lab[p];
        if (gp == p) return p;
        atomicMin(&lab[a], gp);
        a = gp;
    }
}
__device__ __forceinline__ void merge_px(int* lab, int a, int b) {
    for (;;) {
        a = find_root(lab, a);
        b = find_root(lab, b);
        if (a == b) return;
        int mn = min(a, b), mx = max(a, b);
        int old = atomicMin(&lab[mx], mn);
        if (old == mx) return;
        a = mn; b = old;
    }
}

#define SUM121(pp,qq,rr,s0,s1,s2) do { unsigned _c = (pp) & (rr); \
    s0 = (pp) ^ (rr); s1 = _c ^ (qq); s2 = _c & (qq); } while (0)

__device__ __forceinline__ unsigned pack16(float4 a, float4 b, float4 c, float4 d) {
    unsigned r = 0;
    r |= (a.x > 0.5f) ? 1u    : 0u;  r |= (a.y > 0.5f) ? 2u     : 0u;
    r |= (a.z > 0.5f) ? 4u    : 0u;  r |= (a.w > 0.5f) ? 8u     : 0u;
    r |= (b.x > 0.5f) ? 16u   : 0u;  r |= (b.y > 0.5f) ? 32u    : 0u;
    r |= (b.z > 0.5f) ? 64u   : 0u;  r |= (b.w > 0.5f) ? 128u   : 0u;
    r |= (c.x > 0.5f) ? 256u  : 0u;  r |= (c.y > 0.5f) ? 512u   : 0u;
    r |= (c.z > 0.5f) ? 1024u : 0u;  r |= (c.w > 0.5f) ? 2048u  : 0u;
    r |= (d.x > 0.5f) ? 4096u : 0u;  r |= (d.y > 0.5f) ? 8192u  : 0u;
    r |= (d.z > 0.5f) ? 16384u: 0u;  r |= (d.w > 0.5f) ? 32768u : 0u;
    return r;
}

// inclusive-scan a value over groups of 8 lanes; returns EXCLUSIVE prefix (0 for group leader)
__device__ __forceinline__ float scan8_excl(float tot, int lane) {
    float incl = tot;
    #pragma unroll
    for (int o = 1; o < 8; o <<= 1) {
        float t = __shfl_up_sync(0xFFFFFFFFu, incl, o);
        if ((lane & 7) >= o) incl += t;
    }
    return incl - tot;
}

extern __shared__ char smem_raw[];

__global__ __launch_bounds__(NTHREADS)
void fused_hexloss_kernel(const float* __restrict__ preds,
                          const float* __restrict__ templ,
                          float* __restrict__ out, int out_size)
{
    float* sS  = reinterpret_cast<float*>(smem_raw);   // geometry: integral image
    int*   lab = reinterpret_cast<int*>(smem_raw);     // CCL: run-start parents (sparse)

    __shared__ unsigned mbits[NWORDS];       // 2 KB mask
    __shared__ unsigned s_starts[NWORDS];    // CCL run-start bit words
    __shared__ int      s_last[NWORDS];      // CCL last run-start pos per word, or -1
    __shared__ int      s_i0[32], s_i1[32];
    __shared__ float    s_f0[32];

    const int role = blockIdx.x >> 4;        // 0 = geometry, 1 = CCL
    const int img  = blockIdx.x & 15;
    const int tid  = threadIdx.x;
    const int lane = tid & 31;
    const int warp = tid >> 5;
    const unsigned FULL = 0xFFFFFFFFu;

    // ---- mask bits: 16 px/thread, register threshold, one u16 store ----
    const float4* p4 = reinterpret_cast<const float4*>(preds + (size_t)img * NPIX + tid * 16);
    float4 q0 = p4[0], q1 = p4[1], q2 = p4[2], q3 = p4[3];
    const unsigned bits16 = pack16(q0, q1, q2, q3);
    reinterpret_cast<unsigned short*>(mbits)[tid] = (unsigned short)bits16;

    if (role == 0) {
        // =============== GEOMETRY BLOCK: integral (shuffle offsets) + sobel + wsum ===============
        // row scan: 8 consecutive lanes own the 8 segments of one row
        const int rr = tid >> 3, ss = tid & 7;
        float v[16];
        {
            const float4* t4 = reinterpret_cast<const float4*>(templ + rr * 128 + ss * 16);
            float4 a0 = t4[0], a1 = t4[1], a2 = t4[2], a3 = t4[3];
            v[0]=a0.x; v[1]=a0.y; v[2]=a0.z; v[3]=a0.w;
            v[4]=a1.x; v[5]=a1.y; v[6]=a1.z; v[7]=a1.w;
            v[8]=a2.x; v[9]=a2.y; v[10]=a2.z; v[11]=a2.w;
            v[12]=a3.x; v[13]=a3.y; v[14]=a3.z; v[15]=a3.w;
        }
        #pragma unroll
        for (int k = 1; k < 16; ++k) v[k] += v[k - 1];
        const float roff = scan8_excl(v[15], lane);
        {
            float* dst = sS + rr * PITCH + ss * 16;
            #pragma unroll
            for (int k = 0; k < 16; ++k) dst[k] = v[k] + roff;
        }
        int area = __popc(bits16);
        __syncthreads();                     // bar_A: mbits + row-scanned sS

        // column scan: 8 consecutive lanes own the 8 segments of one column
        const int cc = tid >> 3, sg = tid & 7;
        float u[16];
        #pragma unroll
        for (int k = 0; k < 16; ++k) u[k] = sS[(sg * 16 + k) * PITCH + cc];
        #pragma unroll
        for (int k = 1; k < 16; ++k) u[k] += u[k - 1];
        const float coff = scan8_excl(u[15], lane);
        #pragma unroll
        for (int k = 0; k < 16; ++k) sS[(sg * 16 + k) * PITCH + cc] = u[k] + coff;

        // sobel on lower 512 threads (ALU, overlaps col-scan store latency)
        const int chunk = tid & 511;
        const int upper = tid >> 9;
        const int y = chunk >> 2, w = chunk & 3;
        const unsigned cur = mbits[chunk];
        int perim = 0;
        if (!upper) {
            const unsigned prevw = (w > 0) ? mbits[y * 4 + w - 1] : 0u;
            const unsigned nextw = (w < 3) ? mbits[y * 4 + w + 1] : 0u;
            unsigned long long Ac = ((unsigned long long)cur << 1) | (prevw >> 31)
                                  | ((unsigned long long)(nextw & 1u) << 33);
            unsigned long long Aa = 0ULL, Ab = 0ULL;
            if (y > 0) {
                unsigned c0 = mbits[(y-1)*4+w];
                unsigned p0 = (w > 0) ? mbits[(y-1)*4+w-1] : 0u;
                unsigned n0 = (w < 3) ? mbits[(y-1)*4+w+1] : 0u;
                Aa = ((unsigned long long)c0 << 1) | (p0 >> 31) | ((unsigned long long)(n0 & 1u) << 33);
            }
            if (y < 127) {
                unsigned c0 = mbits[(y+1)*4+w];
                unsigned p0 = (w > 0) ? mbits[(y+1)*4+w-1] : 0u;
                unsigned n0 = (w < 3) ? mbits[(y+1)*4+w+1] : 0u;
                Ab = ((unsigned long long)c0 << 1) | (p0 >> 31) | ((unsigned long long)(n0 & 1u) << 33);
            }
            unsigned aL=(unsigned)Aa, aC=(unsigned)(Aa>>1), aR=(unsigned)(Aa>>2);
            unsigned cL=(unsigned)Ac,                       cR=(unsigned)(Ac>>2);
            unsigned bL=(unsigned)Ab, bC=(unsigned)(Ab>>1), bR=(unsigned)(Ab>>2);
            unsigned L0,L1,L2,R0,R1,R2,T0,T1,T2,B0,B1,B2;
            SUM121(aL,cL,bL,L0,L1,L2); SUM121(aR,cR,bR,R0,R1,R2);
            SUM121(aL,aC,aR,T0,T1,T2); SUM121(bL,bC,bR,B0,B1,B2);
            unsigned eqx = ~((L0^R0)|(L1^R1)|(L2^R2));
            unsigned eqy = ~((T0^B0)|(T1^B1)|(T2^B2));
            perim = __popc(~(eqx & eqy));
        }
        __syncthreads();                     // bar_B: integral final

        // wsum: even/odd bit split across half-blocks (all values integer -> float exact)
        float wsumf = 0.0f;
        {
            unsigned m = cur & (upper ? 0xAAAAAAAAu : 0x55555555u);
            const int y1 = min(HH - 1, y + 63);
            const int rb1 = y1 * PITCH;
            const int rb0 = (y > 64) ? (y - 65) * PITCH : -1;
            while (m) {
                int j = __ffs(m) - 1; m &= m - 1;
                int x  = w * 32 + j;
                int x1 = min(WW - 1, x + 63);
                float s = sS[rb1 + x1];
                if (rb0 >= 0) s -= sS[rb0 + x1];
                if (x > 64) {
                    s -= sS[rb1 + (x - 65)];
                    if (rb0 >= 0) s += sS[rb0 + (x - 65)];
                }
                wsumf += s;
            }
        }

        // warp partials exact in float (<= 512*12288 < 2^24); final sum in double, fixed order
        #pragma unroll
        for (int o = 16; o > 0; o >>= 1) {
            area  += __shfl_down_sync(FULL, area,  o);
            perim += __shfl_down_sync(FULL, perim, o);
            wsumf += __shfl_down_sync(FULL, wsumf, o);
        }
        if (lane == 0) { s_i0[warp] = area; s_i1[warp] = perim; s_f0[warp] = wsumf; }
        __syncthreads();                     // bar_C
        if (tid == 0) {
            int A = 0, P = 0; double WS = 0.0;
            #pragma unroll
            for (int q = 0; q < 32; ++q) { A += s_i0[q]; P += s_i1[q]; WS += (double)s_f0[q]; }
            float fa = (float)A, fp = (float)P;
            float compact  = (fp * fp) / (fa + 1e-6f);
            float geometry = (A == 0) ? 0.0f : fabsf(compact - 4.51f);
            float tmpl     = 1.0f - (float)(WS / 16384.0);
            g_geomloss[img] = geometry + tmpl;
        }
    } else {
        // =============== CCL BLOCK: run-based union-find (unchanged from R14) ===============
        __syncthreads();                     // bar1: mbits complete

        const int wd   = tid >> 1;           // word index 0..511
        const int half = tid & 1;
        const int y = wd >> 2, w = wd & 3;
        const unsigned cur   = mbits[wd];
        const unsigned prevw = (w > 0) ? mbits[y * 4 + w - 1] : 0u;
        const unsigned starts = cur & ~((cur << 1) | (prevw >> 31));
        const unsigned halfmask = half ? 0xFFFF0000u : 0x0000FFFFu;
        if (!half) {
            s_starts[wd] = starts;
            s_last[wd]   = starts ? (w * 32 + 31 - __clz(starts)) : -1;
        }
        {
            unsigned m = starts & halfmask;
            const int base = y * 128 + w * 32;
            while (m) {
                int j = __ffs(m) - 1; m &= m - 1;
                lab[base + j] = base + j;
            }
        }
        __syncthreads();                     // bar2: starts/s_last/lab-init visible

        {
            const int r   = tid >> 3;
            const int sub = tid & 7;
            const int ww  = sub >> 1;
            const unsigned hm = (sub & 1) ? 0xFFFF0000u : 0x0000FFFFu;
            if (r < 127) {
                unsigned ov = mbits[r * 4 + ww] & mbits[(r + 1) * 4 + ww];
                if (ov & hm) {
                    unsigned pov = (ww > 0) ? (mbits[r * 4 + ww - 1] & mbits[(r + 1) * 4 + ww - 1]) : 0u;
                    unsigned ssg = (ov & ~((ov << 1) | (pov >> 31))) & hm;
                    while (ssg) {
                        int j = __ffs(ssg) - 1; ssg &= ssg - 1;
                        unsigned below = (2u << j) - 1u;
                        int a, bpos;
                        {
                            unsigned s = s_starts[r * 4 + ww] & below;
                            int pos;
                            if (s) pos = ww * 32 + 31 - __clz(s);
                            else {
                                pos = -1;
                                for (int q = ww - 1; q >= 0 && pos < 0; --q) pos = s_last[r * 4 + q];
                            }
                            a = r * 128 + pos;
                        }
                        {
                            unsigned s = s_starts[(r + 1) * 4 + ww] & below;
                            if (s) bpos = ww * 32 + 31 - __clz(s);
                            else {
                                bpos = -1;
                                for (int q = ww - 1; q >= 0 && bpos < 0; --q) bpos = s_last[(r + 1) * 4 + q];
                            }
                        }
                        merge_px(lab, a, (r + 1) * 128 + bpos);
                    }
                }
            }
        }
        __syncthreads();                     // bar3: union-find complete

        int ncomp = 0;
        {
            unsigned st = starts & halfmask;
            const int base = y * 128 + w * 32;
            while (st) {
                int j = __ffs(st) - 1; st &= st - 1;
                int i = base + j;
                if (lab[i] == i) ncomp++;
            }
        }
        #pragma unroll
        for (int o = 16; o > 0; o >>= 1)
            ncomp += __shfl_down_sync(FULL, ncomp, o);
        if (lane == 0) s_i0[warp] = ncomp;
        __syncthreads();                     // bar4
        if (tid == 0) {
            int C = 0;
            #pragma unroll
            for (int q = 0; q < 32; ++q) C += s_i0[q];
            g_comploss[img] = (float)max(C - 1, 0);
        }
    }

    // =============== last-block finalize (deterministic fixed order) ===============
    if (tid == 0) {
        __threadfence();
        int ticket = atomicAdd(&g_done, 1);
        if (ticket == 2 * NB - 1) {
            double s = 0.0;
            #pragma unroll
            for (int i = 0; i < NB; ++i) s += (double)g_geomloss[i] + (double)g_comploss[i];
            float vv = (float)(s / (double)NB);   // WEIGHT = 1.0
            for (int i = 0; i < out_size; ++i) out[i] = vv;
            g_done = 0;
        }
    }
}

// ---------------------------------------------------------------------------
extern "C" void kernel_launch(void* const* d_in, const int* in_sizes, int n_in,
                              void* d_out, int out_size) {
    const float* preds = (const float*)d_in[0];   // [16,1,128,128]
    const float* templ = (const float*)d_in[1];   // [1,1,128,128]
    (void)in_sizes; (void)n_in;

    const int smem_bytes = HH * PITCH * (int)sizeof(float);   // 66048 B
    cudaFuncSetAttribute(fused_hexloss_kernel,
                         cudaFuncAttributeMaxDynamicSharedMemorySize, smem_bytes);

    fused_hexloss_kernel<<<2 * NB, NTHREADS, smem_bytes>>>(preds, templ, (float*)d_out, out_size);
}

// round 17
// speedup vs baseline: 1.0017x; 1.0017x over previous
#include <cuda_runtime.h>

#define HH 128
#define WW 128
#define NPIX (HH*WW)
#define NWORDS (NPIX/32)   // 512
#define NB 16
#define NTHREADS 1024
#define PITCH 129

__device__ float g_geomloss[NB];
__device__ float g_comploss[NB];
__device__ int   g_done = 0;   // self-resetting ticket (counts to 32)

// ---- lock-free union-find with atomicMin path-halving (monotone => race-safe) ----
__device__ __forceinline__ int find_root(int* lab, int a) {
    for (;;) {
        int p = lab[a];
        if (p == a) return a;
        int gp = lab[p];
        if (gp == p) return p;
        atomicMin(&lab[a], gp);
        a = gp;
    }
}
__device__ __forceinline__ void merge_px(int* lab, int a, int b) {
    for (;;) {
        a = find_root(lab, a);
        b = find_root(lab, b);
        if (a == b) return;
        int mn = min(a, b), mx = max(a, b);
        int old = atomicMin(&lab[mx], mn);
        if (old == mx) return;
        a = mn; b = old;
    }
}

#define SUM121(pp,qq,rr,s0,s1,s2) do { unsigned _c = (pp) & (rr); \
    s0 = (pp) ^ (rr); s1 = _c ^ (qq); s2 = _c & (qq); } while (0)

__device__ __forceinline__ unsigned pack16(float4 a, float4 b, float4 c, float4 d) {
    unsigned r = 0;
    r |= (a.x > 0.5f) ? 1u    : 0u;  r |= (a.y > 0.5f) ? 2u     : 0u;
    r |= (a.z > 0.5f) ? 4u    : 0u;  r |= (a.w > 0.5f) ? 8u     : 0u;
    r |= (b.x > 0.5f) ? 16u   : 0u;  r |= (b.y > 0.5f) ? 32u    : 0u;
    r |= (b.z > 0.5f) ? 64u   : 0u;  r |= (b.w > 0.5f) ? 128u   : 0u;
    r |= (c.x > 0.5f) ? 256u  : 0u;  r |= (c.y > 0.5f) ? 512u   : 0u;
    r |= (c.z > 0.5f) ? 1024u : 0u;  r |= (c.w > 0.5f) ? 2048u  : 0u;
    r |= (d.x > 0.5f) ? 4096u : 0u;  r |= (d.y > 0.5f) ? 8192u  : 0u;
    r |= (d.z > 0.5f) ? 16384u: 0u;  r |= (d.w > 0.5f) ? 32768u : 0u;
    return r;
}

// inclusive-scan a value over groups of 8 lanes; returns EXCLUSIVE prefix (0 for group leader)
__device__ __forceinline__ float scan8_excl(float tot, int lane) {
    float incl = tot;
    #pragma unroll
    for (int o = 1; o < 8; o <<= 1) {
        float t = __shfl_up_sync(0xFFFFFFFFu, incl, o);
        if ((lane & 7) >= o) incl += t;
    }
    return incl - tot;
}

extern __shared__ char smem_raw[];

// minBlocksPerMultiprocessor = 1: allow up to 64 regs/thread -> no local-memory
// spills of the 16-element scan arrays (regs=32 in prior rounds == spilled).
__global__ __launch_bounds__(NTHREADS, 1)
void fused_hexloss_kernel(const float* __restrict__ preds,
                          const float* __restrict__ templ,
                          float* __restrict__ out, int out_size)
{
    float* sS  = reinterpret_cast<float*>(smem_raw);   // geometry: integral image
    int*   lab = reinterpret_cast<int*>(smem_raw);     // CCL: run-start parents (sparse)

    __shared__ unsigned mbits[NWORDS];       // 2 KB mask
    __shared__ unsigned s_starts[NWORDS];    // CCL run-start bit words
    __shared__ int      s_last[NWORDS];      // CCL last run-start pos per word, or -1
    __shared__ int      s_i0[32], s_i1[32];
    __shared__ float    s_f0[32];

    const int role = blockIdx.x >> 4;        // 0 = geometry, 1 = CCL
    const int img  = blockIdx.x & 15;
    const int tid  = threadIdx.x;
    const int lane = tid & 31;
    const int warp = tid >> 5;
    const unsigned FULL = 0xFFFFFFFFu;

    // ---- mask bits: 16 px/thread, register threshold, one u16 store ----
    const float4* p4 = reinterpret_cast<const float4*>(preds + (size_t)img * NPIX + tid * 16);
    float4 q0 = p4[0], q1 = p4[1], q2 = p4[2], q3 = p4[3];
    const unsigned bits16 = pack16(q0, q1, q2, q3);
    reinterpret_cast<unsigned short*>(mbits)[tid] = (unsigned short)bits16;

    if (role == 0) {
        // =============== GEOMETRY BLOCK: integral (shuffle offsets) + sobel + wsum ===============
        const int rr = tid >> 3, ss = tid & 7;
        float v[16];
        {
            const float4* t4 = reinterpret_cast<const float4*>(templ + rr * 128 + ss * 16);
            float4 a0 = t4[0], a1 = t4[1], a2 = t4[2], a3 = t4[3];
            v[0]=a0.x; v[1]=a0.y; v[2]=a0.z; v[3]=a0.w;
            v[4]=a1.x; v[5]=a1.y; v[6]=a1.z; v[7]=a1.w;
            v[8]=a2.x; v[9]=a2.y; v[10]=a2.z; v[11]=a2.w;
            v[12]=a3.x; v[13]=a3.y; v[14]=a3.z; v[15]=a3.w;
        }
        #pragma unroll
        for (int k = 1; k < 16; ++k) v[k] += v[k - 1];
        const float roff = scan8_excl(v[15], lane);
        {
            float* dst = sS + rr * PITCH + ss * 16;
            #pragma unroll
            for (int k = 0; k < 16; ++k) dst[k] = v[k] + roff;
        }
        int area = __popc(bits16);
        __syncthreads();                     // bar_A: mbits + row-scanned sS

        const int cc = tid >> 3, sg = tid & 7;
        float u[16];
        #pragma unroll
        for (int k = 0; k < 16; ++k) u[k] = sS[(sg * 16 + k) * PITCH + cc];
        #pragma unroll
        for (int k = 1; k < 16; ++k) u[k] += u[k - 1];
        const float coff = scan8_excl(u[15], lane);
        #pragma unroll
        for (int k = 0; k < 16; ++k) sS[(sg * 16 + k) * PITCH + cc] = u[k] + coff;

        // sobel on lower 512 threads (ALU, overlaps col-scan store latency)
        const int chunk = tid & 511;
        const int upper = tid >> 9;
        const int y = chunk >> 2, w = chunk & 3;
        const unsigned cur = mbits[chunk];
        int perim = 0;
        if (!upper) {
            const unsigned prevw = (w > 0) ? mbits[y * 4 + w - 1] : 0u;
            const unsigned nextw = (w < 3) ? mbits[y * 4 + w + 1] : 0u;
            unsigned long long Ac = ((unsigned long long)cur << 1) | (prevw >> 31)
                                  | ((unsigned long long)(nextw & 1u) << 33);
            unsigned long long Aa = 0ULL, Ab = 0ULL;
            if (y > 0) {
                unsigned c0 = mbits[(y-1)*4+w];
                unsigned p0 = (w > 0) ? mbits[(y-1)*4+w-1] : 0u;
                unsigned n0 = (w < 3) ? mbits[(y-1)*4+w+1] : 0u;
                Aa = ((unsigned long long)c0 << 1) | (p0 >> 31) | ((unsigned long long)(n0 & 1u) << 33);
            }
            if (y < 127) {
                unsigned c0 = mbits[(y+1)*4+w];
                unsigned p0 = (w > 0) ? mbits[(y+1)*4+w-1] : 0u;
                unsigned n0 = (w < 3) ? mbits[(y+1)*4+w+1] : 0u;
                Ab = ((unsigned long long)c0 << 1) | (p0 >> 31) | ((unsigned long long)(n0 & 1u) << 33);
            }
            unsigned aL=(unsigned)Aa, aC=(unsigned)(Aa>>1), aR=(unsigned)(Aa>>2);
            unsigned cL=(unsigned)Ac,                       cR=(unsigned)(Ac>>2);
            unsigned bL=(unsigned)Ab, bC=(unsigned)(Ab>>1), bR=(unsigned)(Ab>>2);
            unsigned L0,L1,L2,R0,R1,R2,T0,T1,T2,B0,B1,B2;
            SUM121(aL,cL,bL,L0,L1,L2); SUM121(aR,cR,bR,R0,R1,R2);
            SUM121(aL,aC,aR,T0,T1,T2); SUM121(bL,bC,bR,B0,B1,B2);
            unsigned eqx = ~((L0^R0)|(L1^R1)|(L2^R2));
            unsigned eqy = ~((T0^B0)|(T1^B1)|(T2^B2));
            perim = __popc(~(eqx & eqy));
        }
        __syncthreads();                     // bar_B: integral final

        // wsum: even/odd bit split across half-blocks (all values integer -> float exact)
        float wsumf = 0.0f;
        {
            unsigned m = cur & (upper ? 0xAAAAAAAAu : 0x55555555u);
            const int y1 = min(HH - 1, y + 63);
            const int rb1 = y1 * PITCH;
            const int rb0 = (y > 64) ? (y - 65) * PITCH : -1;
            while (m) {
                int j = __ffs(m) - 1; m &= m - 1;
                int x  = w * 32 + j;
                int x1 = min(WW - 1, x + 63);
                float s = sS[rb1 + x1];
                if (rb0 >= 0) s -= sS[rb0 + x1];
                if (x > 64) {
                    s -= sS[rb1 + (x - 65)];
                    if (rb0 >= 0) s += sS[rb0 + (x - 65)];
                }
                wsumf += s;
            }
        }

        #pragma unroll
        for (int o = 16; o > 0; o >>= 1) {
            area  += __shfl_down_sync(FULL, area,  o);
            perim += __shfl_down_sync(FULL, perim, o);
            wsumf += __shfl_down_sync(FULL, wsumf, o);
        }
        if (lane == 0) { s_i0[warp] = area; s_i1[warp] = perim; s_f0[warp] = wsumf; }
        __syncthreads();                     // bar_C
        if (tid == 0) {
            int A = 0, P = 0; double WS = 0.0;
            #pragma unroll
            for (int q = 0; q < 32; ++q) { A += s_i0[q]; P += s_i1[q]; WS += (double)s_f0[q]; }
            float fa = (float)A, fp = (float)P;
            float compact  = (fp * fp) / (fa + 1e-6f);
            float geometry = (A == 0) ? 0.0f : fabsf(compact - 4.51f);
            float tmpl     = 1.0f - (float)(WS / 16384.0);
            g_geomloss[img] = geometry + tmpl;
        }
    } else {
        // =============== CCL BLOCK: run-based union-find ===============
        __syncthreads();                     // bar1: mbits complete

        const int wd   = tid >> 1;           // word index 0..511
        const int half = tid & 1;
        const int y = wd >> 2, w = wd & 3;
        const unsigned cur   = mbits[wd];
        const unsigned prevw = (w > 0) ? mbits[y * 4 + w - 1] : 0u;
        const unsigned starts = cur & ~((cur << 1) | (prevw >> 31));
        const unsigned halfmask = half ? 0xFFFF0000u : 0x0000FFFFu;
        if (!half) {
            s_starts[wd] = starts;
            s_last[wd]   = starts ? (w * 32 + 31 - __clz(starts)) : -1;
        }
        {
            unsigned m = starts & halfmask;
            const int base = y * 128 + w * 32;
            while (m) {
                int j = __ffs(m) - 1; m &= m - 1;
                lab[base + j] = base + j;
            }
        }
        __syncthreads();                     // bar2: starts/s_last/lab-init visible

        {
            const int r   = tid >> 3;
            const int sub = tid & 7;
            const int ww  = sub >> 1;
            const unsigned hm = (sub & 1) ? 0xFFFF0000u : 0x0000FFFFu;
            if (r < 127) {
                unsigned ov = mbits[r * 4 + ww] & mbits[(r + 1) * 4 + ww];
                if (ov & hm) {
                    unsigned pov = (ww > 0) ? (mbits[r * 4 + ww - 1] & mbits[(r + 1) * 4 + ww - 1]) : 0u;
                    unsigned ssg = (ov & ~((ov << 1) | (pov >> 31))) & hm;
                    while (ssg) {
                        int j = __ffs(ssg) - 1; ssg &= ssg - 1;
                        unsigned below = (2u << j) - 1u;
                        int a, bpos;
                        {
                            unsigned s = s_starts[r * 4 + ww] & below;
                            int pos;
                            if (s) pos = ww * 32 + 31 - __clz(s);
                            else {
                                pos = -1;
                                for (int q = ww - 1; q >= 0 && pos < 0; --q) pos = s_last[r * 4 + q];
                            }
                            a = r * 128 + pos;
                        }
                        {
                            unsigned s = s_starts[(r + 1) * 4 + ww] & below;
                            if (s) bpos = ww * 32 + 31 - __clz(s);
                            else {
                                bpos = -1;
                                for (int q = ww - 1; q >= 0 && bpos < 0; --q) bpos = s_last[(r + 1) * 4 + q];
                            }
                        }
                        merge_px(lab, a, (r + 1) * 128 + bpos);
                    }
                }
            }
        }
        __syncthreads();                     // bar3: union-find complete

        int ncomp = 0;
        {
            unsigned st = starts & halfmask;
            const int base = y * 128 + w * 32;
            while (st) {
                int j = __ffs(st) - 1; st &= st - 1;
                int i = base + j;
                if (lab[i] == i) ncomp++;
            }
        }
        #pragma unroll
        for (int o = 16; o > 0; o >>= 1)
            ncomp += __shfl_down_sync(FULL, ncomp, o);
        if (lane == 0) s_i0[warp] = ncomp;
        __syncthreads();                     // bar4
        if (tid == 0) {
            int C = 0;
            #pragma unroll
            for (int q = 0; q < 32; ++q) C += s_i0[q];
            g_comploss[img] = (float)max(C - 1, 0);
        }
    }

    // =============== last-block finalize (deterministic fixed order) ===============
    if (tid == 0) {
        __threadfence();
        int ticket = atomicAdd(&g_done, 1);
        if (ticket == 2 * NB - 1) {
            double s = 0.0;
            #pragma unroll
            for (int i = 0; i < NB; ++i) s += (double)g_geomloss[i] + (double)g_comploss[i];
            float vv = (float)(s / (double)NB);   // WEIGHT = 1.0
            for (int i = 0; i < out_size; ++i) out[i] = vv;
            g_done = 0;
        }
    }
}

// ---------------------------------------------------------------------------
extern "C" void kernel_launch(void* const* d_in, const int* in_sizes, int n_in,
                              void* d_out, int out_size) {
    const float* preds = (const float*)d_in[0];   // [16,1,128,128]
    const float* templ = (const float*)d_in[1];   // [1,1,128,128]
    (void)in_sizes; (void)n_in;

    const int smem_bytes = HH * PITCH * (int)sizeof(float);   // 66048 B
    cudaFuncSetAttribute(fused_hexloss_kernel,
                         cudaFuncAttributeMaxDynamicSharedMemorySize, smem_bytes);

    fused_hexloss_kernel<<<2 * NB, NTHREADS, smem_bytes>>>(preds, templ, (float*)d_out, out_size);
}